// round 8
// baseline (speedup 1.0000x reference)
#include <cuda_runtime.h>
#include <cstdint>

#define VOCAB  50257
#define VPAD   51200
#define SPLITV 12800
#define NTOK   4096
#define MT     128
#define CN     256
#define NCH    50            // chunks per split
#define TOPK   10
#define TILE_F 12288         // floats per kc tile (256n x 48k)
#define AF_F   24576         // A fragment floats (128 x 192)
#define BS_OFF AF_F
#define LG_OFF (AF_F + 2*TILE_F)   // 49152
#define LG_STR 65
#define SMEM_MAIN ((LG_OFF + 128*LG_STR) * 4)   // 229,888 B
#define SMEM_FIN  (25536 * 4)

// reduced embeddings in B-fragment order:
// float4 slot = ((nb*4 + kc)*3 + sp2)*1024 + na*32 + lane
// value: {B(s=2sp2,p0), B(s,p1), B(s+1,p0), B(s+1,p1)},  B(s,p)[k=s*8+t+4p][n=na*8+g] = 4*emb[n][4k]
__device__ float g_erf[(size_t)VPAD * 192];
__device__ float g_pv[4][NTOK][TOPK];
__device__ int   g_pi[4][NTOK][TOPK];
__device__ float g_ps[4][NTOK];

#define CP_COMMIT asm volatile("cp.async.commit_group;" ::: "memory")
#define CP_WAIT1  asm volatile("cp.async.wait_group 1;" ::: "memory")
#define CP_WAIT0  asm volatile("cp.async.wait_group 0;" ::: "memory")

__device__ __forceinline__ void cp16(float* s, const float* g) {
    unsigned sa = (unsigned)__cvta_generic_to_shared(s);
    asm volatile("cp.async.cg.shared.global [%0], [%1], 16;" :: "r"(sa), "l"(g));
}
__device__ __forceinline__ float to_tf32(float x) {
    unsigned u; asm("cvt.rna.tf32.f32 %0, %1;" : "=r"(u) : "f"(x));
    return __uint_as_float(u);
}
__device__ __forceinline__ void mma8(float* d, float4 a, float b0, float b1) {
    asm volatile("mma.sync.aligned.m16n8k8.row.col.f32.tf32.tf32.f32 "
        "{%0,%1,%2,%3}, {%4,%5,%6,%7}, {%8,%9}, {%0,%1,%2,%3};"
        : "+f"(d[0]), "+f"(d[1]), "+f"(d[2]), "+f"(d[3])
        : "r"(__float_as_uint(a.x)), "r"(__float_as_uint(a.y)),
          "r"(__float_as_uint(a.z)), "r"(__float_as_uint(a.w)),
          "r"(__float_as_uint(b0)),  "r"(__float_as_uint(b1)));
}
__device__ __forceinline__ void tk_insert(float v, int gi, float* tv, int* ti_, float& minv, int& minp) {
    tv[minp] = v; ti_[minp] = gi;
    minv = tv[0]; minp = 0;
#pragma unroll
    for (int q = 1; q < TOPK; q++) if (tv[q] < minv) { minv = tv[q]; minp = q; }
}

// ---------- prep: write g_erf in B-fragment order ----------
__global__ void __launch_bounds__(256)
prep_kernel(const float* __restrict__ emb) {
    int flat = blockIdx.x * 256 + threadIdx.x;       // float4 slot
    int lane = flat & 31;
    int na   = (flat >> 5) & 31;
    int r    = flat >> 10;                           // (nb*4+kc)*3 + sp2
    int sp2  = r % 3;
    int t2   = r / 3;
    int kc   = t2 & 3, nb = t2 >> 2;
    int v  = nb * 256 + na * 8 + (lane >> 2);
    int kr = kc * 48 + sp2 * 16 + (lane & 3);
    float4 o = make_float4(0.f, 0.f, 0.f, 0.f);
    if (v < VOCAB) {
        const float* e = emb + (size_t)v * 768 + 4 * kr;
        o.x = to_tf32(4.0f * __ldg(e + 0));
        o.y = to_tf32(4.0f * __ldg(e + 16));
        o.z = to_tf32(4.0f * __ldg(e + 32));
        o.w = to_tf32(4.0f * __ldg(e + 48));
    }
    ((float4*)g_erf)[flat] = o;
}

__device__ __forceinline__ void copy_tile(float* BS, int nb0, int gidx, int tid) {
    const float* src = g_erf + ((size_t)(nb0 + (gidx >> 2)) * 4 + (gidx & 3)) * TILE_F;
    float* dst = BS + (gidx & 1) * TILE_F;
#pragma unroll
    for (int i = 0; i < 12; i++) {
        int o = (tid + i * 256) * 4;
        cp16(dst + o, src + o);
    }
    CP_COMMIT;
}

// ---------- main: tf32 mma.sync GEMM + fused poly-softmax-sum + top-k ----------
__global__ void __launch_bounds__(256, 1)
main_kernel(const float* __restrict__ x) {
    extern __shared__ float sm[];
    float* AF = sm;
    float* BS = sm + BS_OFF;
    float* LG = sm + LG_OFF;
    const int tid = threadIdx.x, lane = tid & 31, warp = tid >> 5;
    const int warpm = warp >> 2, warpn = warp & 3;
    const int mt = blockIdx.x >> 2, sp = blockIdx.x & 3;
    const int m0 = mt * MT;
    const int v0 = sp * SPLITV;
    const int nb0 = sp * NCH;

    // stage A fragments (tf32)
    for (int idx = tid; idx < AF_F; idx += 256) {
        int j = idx & 3, li = (idx >> 2) & 31, ma = (idx >> 7) & 7, s = idx >> 10;
        int g = li >> 2, t = li & 3;
        int row = ma * 16 + g + ((j & 1) << 3);
        int col = s * 8 + t + ((j >> 1) << 2);
        AF[idx] = to_tf32(__ldg(x + (size_t)(m0 + row) * 768 + 4 * col));
    }

    // scan state
    float tv[TOPK]; int ti_[TOPK];
#pragma unroll
    for (int i = 0; i < TOPK; i++) { tv[i] = -1e30f; ti_[i] = 0; }
    float minv = -1e30f; int minp = 0; float sumexp = 0.0f;
    const int row_s = tid & 127, half = tid >> 7;
    const int xr = (row_s & 3) << 2;
    float* scanbase = LG + row_s * LG_STR;

    __syncthreads();

    copy_tile(BS, nb0, 0, tid);
    copy_tile(BS, nb0, 1, tid);

    for (int ch = 0; ch < NCH; ch++) {
        float acc[4][8][4];
#pragma unroll
        for (int ma = 0; ma < 4; ma++)
#pragma unroll
            for (int j = 0; j < 8; j++)
#pragma unroll
                for (int e = 0; e < 4; e++) acc[ma][j][e] = 0.0f;

#pragma unroll 1
        for (int kc = 0; kc < 4; kc++) {
            int g = ch * 4 + kc;
            if (g + 2 < NCH * 4) { CP_WAIT1; } else { CP_WAIT0; }
            __syncthreads();
            const float* Bb = BS + (g & 1) * TILE_F;
#pragma unroll
            for (int sp2 = 0; sp2 < 3; sp2++) {
                int s_abs = kc * 6 + sp2 * 2;
                float4 a0[4], a1[4];
#pragma unroll
                for (int ma = 0; ma < 4; ma++) {
                    a0[ma] = *(const float4*)(AF + (((s_abs    ) * 8 + warpm * 4 + ma) * 32 + lane) * 4);
                    a1[ma] = *(const float4*)(AF + (((s_abs + 1) * 8 + warpm * 4 + ma) * 32 + lane) * 4);
                }
#pragma unroll
                for (int j = 0; j < 8; j++) {
                    float4 bb = *(const float4*)(Bb + ((sp2 * 32 + warpn * 8 + j) * 32 + lane) * 4);
#pragma unroll
                    for (int ma = 0; ma < 4; ma++) mma8(acc[ma][j], a0[ma], bb.x, bb.y);
#pragma unroll
                    for (int ma = 0; ma < 4; ma++) mma8(acc[ma][j], a1[ma], bb.z, bb.w);
                }
            }
            __syncthreads();
            if (g + 2 < NCH * 4) copy_tile(BS, nb0, g + 2, tid);
        }

        // spill + scan in 4 quarters (16 cols per warp per quarter)
        const int chbase = v0 + ch * CN;
#pragma unroll 1
        for (int q = 0; q < 4; q++) {
#pragma unroll
            for (int ma = 0; ma < 4; ma++)
#pragma unroll
                for (int jj = 0; jj < 2; jj++) {
                    int j = 2 * q + jj;
                    int rl = warpm * 64 + ma * 16 + (lane >> 2);
                    int c  = warpn * 16 + jj * 8 + 2 * (lane & 3);
                    int xw = (rl & 3) << 2;
                    LG[rl * LG_STR + (c ^ xw)]           = acc[ma][j][0];
                    LG[rl * LG_STR + ((c + 1) ^ xw)]     = acc[ma][j][1];
                    LG[(rl + 8) * LG_STR + (c ^ xw)]     = acc[ma][j][2];
                    LG[(rl + 8) * LG_STR + ((c + 1) ^ xw)] = acc[ma][j][3];
                }
            __syncthreads();
            const int qb = chbase + (q << 4);
#pragma unroll 8
            for (int i = 0; i < 32; i++) {
                int c = half * 32 + i;
                float l = scanbase[c ^ xr];
                int n_g = qb + ((c >> 4) << 6) + (c & 15);
                if (n_g < VOCAB) {
                    float e = 1.0f + l * (1.0f + l * (0.5f + l * (0.16666667f + l * 0.041666668f)));
                    sumexp += e;
                    if (l > minv) tk_insert(l, n_g, tv, ti_, minv, minp);
                }
            }
            __syncthreads();
        }
    }

    // merge 2 scanners per token (overlay on LG), write split partials
    float* MV = LG;
    int*   MI = (int*)(LG + 2560);
    float* MS = LG + 5120;
#pragma unroll
    for (int i = 0; i < TOPK; i++) { MV[tid * TOPK + i] = tv[i]; MI[tid * TOPK + i] = ti_[i]; }
    MS[tid] = sumexp;
    __syncthreads();
    if (tid < 128) {
        float bv[TOPK]; int bi[TOPK];
#pragma unroll
        for (int j = 0; j < TOPK; j++) { bv[j] = MV[tid * TOPK + j]; bi[j] = MI[tid * TOPK + j]; }
        float bmin = bv[0]; int bmp = 0;
#pragma unroll
        for (int q = 1; q < TOPK; q++) if (bv[q] < bmin) { bmin = bv[q]; bmp = q; }
#pragma unroll
        for (int e = 0; e < TOPK; e++) {
            float v2 = MV[(tid + 128) * TOPK + e];
            if (v2 > bmin) tk_insert(v2, MI[(tid + 128) * TOPK + e], bv, bi, bmin, bmp);
        }
        int t = m0 + tid;
#pragma unroll
        for (int j = 0; j < TOPK; j++) { g_pv[sp][t][j] = bv[j]; g_pi[sp][t][j] = bi[j]; }
        g_ps[sp][t] = MS[tid] + MS[tid + 128];
    }
}

// ---------- finalize: merge splits, exact rescore, output ----------
__global__ void __launch_bounds__(256)
final_kernel(const float* __restrict__ x, const float* __restrict__ emb,
             float* __restrict__ out) {
    extern __shared__ float sm2[];
    float* XF = sm2;                        // [32][768]
    int*   CI = (int*)(sm2 + 24576);        // [320]
    float* CS = sm2 + 24896;                // [320]
    float* EX = sm2 + 25216;                // [320]
    const int tid = threadIdx.x;
    const int t0 = blockIdx.x * 32;

    if (tid < 32) {
        int t = t0 + tid;
        float bv[TOPK]; int bi[TOPK];
#pragma unroll
        for (int j = 0; j < TOPK; j++) { bv[j] = g_pv[0][t][j]; bi[j] = g_pi[0][t][j]; }
        float bmin = bv[0]; int bmp = 0;
#pragma unroll
        for (int q = 1; q < TOPK; q++) if (bv[q] < bmin) { bmin = bv[q]; bmp = q; }
#pragma unroll 1
        for (int s = 1; s < 4; s++) {
#pragma unroll
            for (int e = 0; e < TOPK; e++) {
                float v2 = g_pv[s][t][e];
                if (v2 > bmin) tk_insert(v2, g_pi[s][t][e], bv, bi, bmin, bmp);
            }
        }
        float S = g_ps[0][t] + g_ps[1][t] + g_ps[2][t] + g_ps[3][t];
        float invS = 1.0f / S;
#pragma unroll
        for (int j = 0; j < TOPK; j++) {
            CI[tid * TOPK + j] = bi[j];
            CS[tid * TOPK + j] = __expf(bv[j]) * invS;
        }
    }
    __syncthreads();

    for (int idx = tid; idx < 32 * 768; idx += 256)
        XF[idx] = x[(size_t)t0 * 768 + idx];
    __syncthreads();

#pragma unroll 1
    for (int it = 0; it < 10; it++) {
        int slot = it * 256 + tid;
        int p = slot >> 3, q = slot & 7;
        int e = CI[p];
        const float4* er = (const float4*)(emb + (size_t)e * 768);
        const float4* xrp = (const float4*)(XF + (p / TOPK) * 768);
        float d = 0.0f;
#pragma unroll
        for (int t = 0; t < 24; t++) {
            float4 ev = er[q + (t << 3)];
            float4 xv = xrp[q + (t << 3)];
            d += ev.x * xv.x + ev.y * xv.y + ev.z * xv.z + ev.w * xv.w;
        }
        d += __shfl_xor_sync(0xffffffffu, d, 4);
        d += __shfl_xor_sync(0xffffffffu, d, 2);
        d += __shfl_xor_sync(0xffffffffu, d, 1);
        if (q == 0) EX[p] = d;
    }
    __syncthreads();

    if (tid < 32) {
        float ex[TOPK]; float mx = -1e30f;
#pragma unroll
        for (int j = 0; j < TOPK; j++) { ex[j] = EX[tid * TOPK + j]; mx = fmaxf(mx, ex[j]); }
        float se = 0.0f;
#pragma unroll
        for (int j = 0; j < TOPK; j++) { ex[j] = __expf(ex[j] - mx); se += ex[j]; }
        float inv = 1.0f / se;
        float best = -1e30f;
#pragma unroll
        for (int j = 0; j < TOPK; j++)
            best = fmaxf(best, 0.5f * (ex[j] * inv + CS[tid * TOPK + j]));
        out[t0 + tid] = best;
    }
}

extern "C" void kernel_launch(void* const* d_in, const int* in_sizes, int n_in,
                              void* d_out, int out_size) {
    const float* x   = (const float*)d_in[0];
    const float* emb = (const float*)d_in[1];
    if (n_in >= 2 && in_sizes[0] > in_sizes[1]) {
        const float* t = x; x = emb; emb = t;
    }
    cudaFuncSetAttribute(main_kernel,  cudaFuncAttributeMaxDynamicSharedMemorySize, SMEM_MAIN);
    cudaFuncSetAttribute(final_kernel, cudaFuncAttributeMaxDynamicSharedMemorySize, SMEM_FIN);
    prep_kernel<<<(VPAD * 192 / 4) / 256, 256>>>(emb);
    main_kernel<<<128, 256, SMEM_MAIN>>>(x);
    final_kernel<<<NTOK / 32, 256, SMEM_FIN>>>(x, emb, (float*)d_out);
}

// round 10
// speedup vs baseline: 1.0091x; 1.0091x over previous
#include <cuda_runtime.h>
#include <cstdint>

#define VOCAB  50257
#define VPAD   50688          // 99 * 512
#define NTOK   4096
#define TM     32             // tokens per CTA
#define TN     512            // vocab candidates per chunk
#define KC     16             // k-chunk
#define NKC    12             // 192/16
#define TOPK   10

// dynamic smem layout (float offsets)
#define OFF_XS 0              // [192][36]  x reduced, transposed, *4
#define OFF_BS 6912           // [2][16][512] double-buffered er chunk
#define OFF_LG 23296          // [256][17]  quarter logit tile (32 tok * 8 scanners * 16+1)
#define SMEM_FLOATS 27648
#define SMEM_MAIN (SMEM_FLOATS * 4)   // 110,592 B -> 2 CTAs/SM
#define SMEM_FIN  (25536 * 4)

// reduced embeddings, transposed [k][v], zero-padded to VPAD
__device__ float g_ert[(size_t)192 * VPAD];
__device__ float g_pv[2][NTOK][TOPK];
__device__ int   g_pi[2][NTOK][TOPK];
__device__ float g_ps[2][NTOK];

__device__ __forceinline__ void cp16(float* s, const float* g) {
    unsigned sa = (unsigned)__cvta_generic_to_shared(s);
    asm volatile("cp.async.cg.shared.global [%0], [%1], 16;" :: "r"(sa), "l"(g));
}
__device__ __forceinline__ unsigned long long pack2(float v) {
    unsigned long long r;
    asm("mov.b64 %0, {%1, %2};" : "=l"(r) : "f"(v), "f"(v));
    return r;
}
__device__ __forceinline__ void fma2(unsigned long long& d, unsigned long long a, unsigned long long b) {
    asm("fma.rn.f32x2 %0, %1, %2, %0;" : "+l"(d) : "l"(a), "l"(b));
}
__device__ __forceinline__ void tk_insert(float v, int gi, float* tv, int* ti_, float& minv, int& minp) {
    tv[minp] = v; ti_[minp] = gi;
    minv = tv[0]; minp = 0;
#pragma unroll
    for (int q = 1; q < TOPK; q++) if (tv[q] < minv) { minv = tv[q]; minp = q; }
}

// ---------- prep: g_ert[k][v] = emb[v][4k] ----------
__global__ void __launch_bounds__(256)
prep_kernel(const float* __restrict__ emb) {
    __shared__ float smp[48][193];
    const int vb = blockIdx.x * 48;
    for (int idx = threadIdx.x; idx < 48 * 192; idx += 256) {
        int vl = idx / 192, k = idx - vl * 192;
        int v = vb + vl;
        smp[vl][k] = (v < VOCAB) ? emb[(size_t)v * 768 + 4 * k] : 0.0f;
    }
    __syncthreads();
    for (int idx = threadIdx.x; idx < 48 * 192; idx += 256) {
        int k = idx / 48, vl = idx - k * 48;
        g_ert[(size_t)k * VPAD + vb + vl] = smp[vl][k];
    }
}

// ---------- main: FFMA2 GEMM + fused softmax-sum + top-k, 2 CTAs/SM ----------
__global__ void __launch_bounds__(256, 2)
main_kernel(const float* __restrict__ x) {
    extern __shared__ float sm[];
    float* XS = sm + OFF_XS;
    float* BS = sm + OFF_BS;
    float* LG = sm + OFF_LG;
    const int tid = threadIdx.x;
    const int ty = tid >> 6;        // 0..3
    const int tx = tid & 63;        // 0..63
    const int mt = blockIdx.x >> 1, sp = blockIdx.x & 1;
    const int m0 = mt * TM;
    const int chb = sp ? 50 : 0, che = sp ? 99 : 50;

    // stage x reduced (transposed [k][m], scale 4 = sqrt(R)^2 folded in)
    for (int idx = tid; idx < TM * 192; idx += 256) {
        int m = idx / 192, k = idx - m * 192;
        XS[k * 36 + m] = 4.0f * x[(size_t)(m0 + m) * 768 + 4 * k];
    }

    // per-thread scan state: token sM = tid>>3, scanner slot sS = tid&7
    float tv[TOPK]; int ti_[TOPK];
#pragma unroll
    for (int i = 0; i < TOPK; i++) { tv[i] = -1e30f; ti_[i] = 0; }
    float minv = -1e30f; int minp = 0;
    float sumexp = 0.0f;
    const int sS = tid & 7, sM = tid >> 3;

    __syncthreads();

    // preload chunk chb, kc=0 into buffer 0
    {
        const float* src = g_ert + chb * TN;
#pragma unroll
        for (int i = 0; i < 8; i++) {
            int pos = i * 256 + tid;
            int r = pos >> 7, c4 = (pos & 127) << 2;
            cp16(BS + r * TN + c4, src + (size_t)r * VPAD + c4);
        }
        asm volatile("cp.async.commit_group;" ::: "memory");
    }

    for (int ch = chb; ch < che; ch++) {
        const int c0 = ch * TN;
        unsigned long long acc[8][4];
#pragma unroll
        for (int i = 0; i < 8; i++)
#pragma unroll
            for (int j = 0; j < 4; j++) acc[i][j] = 0ull;

        for (int kc = 0; kc < NKC; kc++) {
            if (kc + 1 < NKC) {
                const float* src = g_ert + (size_t)(kc + 1) * KC * VPAD + c0;
                float* dst = BS + ((kc + 1) & 1) * (KC * TN);
#pragma unroll
                for (int i = 0; i < 8; i++) {
                    int pos = i * 256 + tid;
                    int r = pos >> 7, c4 = (pos & 127) << 2;
                    cp16(dst + r * TN + c4, src + (size_t)r * VPAD + c4);
                }
                asm volatile("cp.async.commit_group;" ::: "memory");
                asm volatile("cp.async.wait_group 1;" ::: "memory");
            } else {
                asm volatile("cp.async.wait_group 0;" ::: "memory");
            }
            __syncthreads();
            const float* Bp = BS + (kc & 1) * (KC * TN) + (tx << 3);
            const float* Ap = XS + kc * KC * 36 + (ty << 3);
#pragma unroll 4
            for (int k = 0; k < KC; k++) {
                const float4 a0 = *(const float4*)(Ap + k * 36);
                const float4 a1 = *(const float4*)(Ap + k * 36 + 4);
                const ulonglong2 b01 = *(const ulonglong2*)(Bp + (k << 9));
                const ulonglong2 b23 = *(const ulonglong2*)(Bp + (k << 9) + 4);
                unsigned long long bb[4] = {b01.x, b01.y, b23.x, b23.y};
                float av[8] = {a0.x, a0.y, a0.z, a0.w, a1.x, a1.y, a1.z, a1.w};
#pragma unroll
                for (int i = 0; i < 8; i++) {
                    unsigned long long ap = pack2(av[i]);
#pragma unroll
                    for (int j = 0; j < 4; j++) fma2(acc[i][j], ap, bb[j]);
                }
            }
            __syncthreads();
        }

        // prefetch next chunk's kc=0 during the scan phase (overlap)
        if (ch + 1 < che) {
            const float* src = g_ert + (size_t)(ch + 1) * TN;
#pragma unroll
            for (int i = 0; i < 8; i++) {
                int pos = i * 256 + tid;
                int r = pos >> 7, c4 = (pos & 127) << 2;
                cp16(BS + r * TN + c4, src + (size_t)r * VPAD + c4);
            }
            asm volatile("cp.async.commit_group;" ::: "memory");
        }

        // spill + scan in 4 quarters of 128 columns
        const int q_own = tx >> 4;        // this thread's cols live in quarter q_own
        const int t15 = tx & 15;
        const int cb = (t15 & 1) << 3;    // col base within scanner's 16
        const int srow = t15 >> 1;        // scanner slot
#pragma unroll 1
        for (int q = 0; q < 4; q++) {
            if (q_own == q) {
#pragma unroll
                for (int i = 0; i < 8; i++) {
                    float* dst = LG + ((((ty << 3) + i) << 3) + srow) * 17 + cb;
#pragma unroll
                    for (int p = 0; p < 4; p++) {
                        dst[2 * p]     = __uint_as_float((unsigned)(acc[i][p] & 0xffffffffull));
                        dst[2 * p + 1] = __uint_as_float((unsigned)(acc[i][p] >> 32));
                    }
                }
            }
            __syncthreads();
            {
                const float* row = LG + tid * 17;
                const int gb = c0 + (q << 7) + (sS << 4);
#pragma unroll
                for (int c = 0; c < 16; c++) {
                    float l = row[c];
                    int n_g = gb + c;
                    if (n_g < VOCAB) {
                        sumexp += __expf(l);
                        if (l > minv) tk_insert(l, n_g, tv, ti_, minv, minp);
                    }
                }
            }
            __syncthreads();
        }
    }

    // dump per-scanner state (overlay on XS region) and merge 8 scanners/token
    float* MV = sm;
    int*   MI = (int*)(sm + 2560);
    float* MS = sm + 5120;
#pragma unroll
    for (int i = 0; i < TOPK; i++) { MV[tid * TOPK + i] = tv[i]; MI[tid * TOPK + i] = ti_[i]; }
    MS[tid] = sumexp;
    __syncthreads();
    if (tid < TM) {
        const int m = tid;
        float bv[TOPK]; int bi[TOPK];
#pragma unroll
        for (int j = 0; j < TOPK; j++) { bv[j] = MV[m * 80 + j]; bi[j] = MI[m * 80 + j]; }
        float bmin = bv[0]; int bmp = 0;
#pragma unroll
        for (int q = 1; q < TOPK; q++) if (bv[q] < bmin) { bmin = bv[q]; bmp = q; }
        for (int e = TOPK; e < 8 * TOPK; e++) {
            float v = MV[m * 80 + e];
            if (v > bmin) tk_insert(v, MI[m * 80 + e], bv, bi, bmin, bmp);
        }
        float S = 0.0f;
#pragma unroll
        for (int s = 0; s < 8; s++) S += MS[m * 8 + s];
        int t = m0 + m;
#pragma unroll
        for (int j = 0; j < TOPK; j++) { g_pv[sp][t][j] = bv[j]; g_pi[sp][t][j] = bi[j]; }
        g_ps[sp][t] = S;
    }
}

// ---------- finalize: merge 2 splits, exact rescore, output ----------
__global__ void __launch_bounds__(256)
final_kernel(const float* __restrict__ x, const float* __restrict__ emb,
             float* __restrict__ out) {
    extern __shared__ float sm2[];
    float* XF = sm2;                        // [32][768]
    int*   CI = (int*)(sm2 + 24576);        // [320]
    float* CS = sm2 + 24896;                // [320]
    float* EX = sm2 + 25216;                // [320]
    const int tid = threadIdx.x;
    const int t0 = blockIdx.x * 32;

    if (tid < 32) {
        int t = t0 + tid;
        float bv[TOPK]; int bi[TOPK];
#pragma unroll
        for (int j = 0; j < TOPK; j++) { bv[j] = g_pv[0][t][j]; bi[j] = g_pi[0][t][j]; }
        float bmin = bv[0]; int bmp = 0;
#pragma unroll
        for (int q = 1; q < TOPK; q++) if (bv[q] < bmin) { bmin = bv[q]; bmp = q; }
#pragma unroll
        for (int e = 0; e < TOPK; e++) {
            float v2 = g_pv[1][t][e];
            if (v2 > bmin) tk_insert(v2, g_pi[1][t][e], bv, bi, bmin, bmp);
        }
        float S = g_ps[0][t] + g_ps[1][t];
        float invS = 1.0f / S;
#pragma unroll
        for (int j = 0; j < TOPK; j++) {
            CI[tid * TOPK + j] = bi[j];
            CS[tid * TOPK + j] = __expf(bv[j]) * invS;
        }
    }
    __syncthreads();

    for (int idx = tid; idx < 32 * 768; idx += 256)
        XF[idx] = x[(size_t)t0 * 768 + idx];
    __syncthreads();

    // exact rescore: 320 (token,cand) pairs, 8 lanes per pair, coalesced gather
#pragma unroll 1
    for (int it = 0; it < 10; it++) {
        int slot = it * 256 + tid;
        int p = slot >> 3, q = slot & 7;
        int e = CI[p];
        const float4* er = (const float4*)(emb + (size_t)e * 768);
        const float4* xrp = (const float4*)(XF + (p / TOPK) * 768);
        float d = 0.0f;
#pragma unroll
        for (int t = 0; t < 24; t++) {
            float4 ev = er[q + (t << 3)];
            float4 xv = xrp[q + (t << 3)];
            d += ev.x * xv.x + ev.y * xv.y + ev.z * xv.z + ev.w * xv.w;
        }
        d += __shfl_xor_sync(0xffffffffu, d, 4);
        d += __shfl_xor_sync(0xffffffffu, d, 2);
        d += __shfl_xor_sync(0xffffffffu, d, 1);
        if (q == 0) EX[p] = d;
    }
    __syncthreads();

    if (tid < 32) {
        float ex[TOPK]; float mx = -1e30f;
#pragma unroll
        for (int j = 0; j < TOPK; j++) { ex[j] = EX[tid * TOPK + j]; mx = fmaxf(mx, ex[j]); }
        float se = 0.0f;
#pragma unroll
        for (int j = 0; j < TOPK; j++) { ex[j] = __expf(ex[j] - mx); se += ex[j]; }
        float inv = 1.0f / se;
        float best = -1e30f;
#pragma unroll
        for (int j = 0; j < TOPK; j++)
            best = fmaxf(best, 0.5f * (ex[j] * inv + CS[tid * TOPK + j]));
        out[t0 + tid] = best;
    }
}

extern "C" void kernel_launch(void* const* d_in, const int* in_sizes, int n_in,
                              void* d_out, int out_size) {
    const float* x   = (const float*)d_in[0];
    const float* emb = (const float*)d_in[1];
    if (n_in >= 2 && in_sizes[0] > in_sizes[1]) {   // embeddings is the larger tensor
        const float* t = x; x = emb; emb = t;
    }
    cudaFuncSetAttribute(main_kernel,  cudaFuncAttributeMaxDynamicSharedMemorySize, SMEM_MAIN);
    cudaFuncSetAttribute(final_kernel, cudaFuncAttributeMaxDynamicSharedMemorySize, SMEM_FIN);
    prep_kernel<<<VPAD / 48, 256>>>(emb);
    main_kernel<<<256, 256, SMEM_MAIN>>>(x);
    final_kernel<<<NTOK / 32, 256, SMEM_FIN>>>(x, emb, (float*)d_out);
}